// round 2
// baseline (speedup 1.0000x reference)
#include <cuda_runtime.h>
#include <math.h>

// Problem constants
#define BB 32
#define LL 2880
#define CC 862
#define PREDP 720
#define SEGS 48
#define NMM 4
#define KK 16
#define STRIDEV 8
#define NINV 60
#define NOUTV 15
#define CDIMV 359

#define CPB 8              // channels per block
#define XROW 2884          // padded smem row length (floats), 2884 % 32 == 4
#define NTHR 256
#define CBLKS ((CC + CPB - 1) / CPB)   // 108

// dynamic smem layout (floats):
//   xs   : CPB*XROW = 23072   raw x -> xn -> (reused) staged outputs
//   wbuf : 3600               reductions, then W_eff per 4-channel group
//   cw   : 128                conv weights for 8 channels
//   gts  : 32                 gate values [8][4]
//   meanv/stdv/istdv : 8 each
//   beff : 60                 gated map bias [4][15]
//   cbs  : 8                  conv bias
#define SMEM_FLOATS (CPB*XROW + 3600 + 128 + 32 + 8 + 8 + 8 + 60 + 8)

__global__ __launch_bounds__(NTHR, 2)
void fused_model_kernel(const float* __restrict__ x,
                        const float* __restrict__ conv_w,
                        const float* __restrict__ conv_b,
                        const float* __restrict__ gate_w,
                        const float* __restrict__ gate_b,
                        const float* __restrict__ map_w,
                        const float* __restrict__ map_b,
                        float* __restrict__ out)
{
    extern __shared__ float sm[];
    float* xs    = sm;                    // 23072
    float* wbuf  = xs + CPB * XROW;       // 3600
    float* cw    = wbuf + 3600;           // 128
    float* gts   = cw + 128;              // 32
    float* meanv = gts + 32;              // 8
    float* stdv  = meanv + 8;             // 8
    float* istdv = stdv + 8;              // 8
    float* beff  = istdv + 8;             // 60
    float* cbs   = beff + 60;             // 8

    const int t  = threadIdx.x;
    const int b  = blockIdx.x / CBLKS;
    const int c0 = (blockIdx.x % CBLKS) * CPB;

    // ---- phase 0: per-channel conv weights/bias ----
    if (t < CPB * KK) {
        int ch = t >> 4, k = t & 15;
        int c = c0 + ch;
        cw[t] = (c < CC) ? conv_w[c * KK + k] : 0.f;
    }
    if (t < CPB) {
        int c = c0 + t;
        cbs[t] = (c < CC) ? conv_b[c] : 0.f;
    }

    // ---- phase 1: load x slice + accumulate stats ----
    {
        const int ch = t & 7, lt = t >> 3;      // 8 channels x 32 lanes
        const int c = c0 + ch;
        const bool valid = (c < CC);
        const float* xb = x + (size_t)b * LL * CC + c;
        float* row = xs + ch * XROW;
        float s = 0.f, s2 = 0.f;
        #pragma unroll 5
        for (int l = lt; l < LL; l += 32) {
            float v = valid ? __ldg(xb + (size_t)l * CC) : 0.f;
            row[l] = v;
            s += v;
            s2 = fmaf(v, v, s2);
        }
        wbuf[ch * 32 + lt] = s;
        wbuf[256 + ch * 32 + lt] = s2;
    }
    __syncthreads();
    if (t < CPB) {
        float s = 0.f, s2 = 0.f;
        #pragma unroll
        for (int i = 0; i < 32; i++) { s += wbuf[t * 32 + i]; s2 += wbuf[256 + t * 32 + i]; }
        float mean = s * (1.f / LL);
        float var  = fmaxf(s2 * (1.f / LL) - mean * mean, 0.f);
        float sd   = sqrtf(var + 1e-10f);
        meanv[t] = mean;
        stdv[t]  = sd;
        istdv[t] = 1.f / sd;
    }
    __syncthreads();

    // ---- phase 2: normalize in place ----
    {
        const int ch = t & 7, lt = t >> 3;
        const float mean = meanv[ch], is = istdv[ch];
        float* row = xs + ch * XROW;
        #pragma unroll 5
        for (int l = lt; l < LL; l += 32)
            row[l] = (row[l] - mean) * is;
    }
    __syncthreads();

    // ---- phase 3: depthwise conv + gate logit partials ----
    {
        const int ch = t & 7, dl = t >> 3;      // 32 d-lanes per channel
        const int d0 = dl * 12;
        const int dend = (d0 + 12 < CDIMV) ? d0 + 12 : CDIMV;
        float a0 = 0.f, a1 = 0.f, a2 = 0.f, a3 = 0.f;
        if (d0 < dend) {
            const float4* kwp = (const float4*)(cw + ch * 16);
            const float4 kA = kwp[0], kB = kwp[1], kC = kwp[2], kD = kwp[3];
            const float cb = cbs[ch];
            const float* row = xs + ch * XROW;
            const float4* base = (const float4*)(row + 8 * d0);
            float4 w0 = base[0], w1 = base[1], w2 = base[2], w3 = base[3];
            for (int d = d0; d < dend; d++) {
                float cv = cb;
                cv = fmaf(w0.x, kA.x, cv); cv = fmaf(w0.y, kA.y, cv);
                cv = fmaf(w0.z, kA.z, cv); cv = fmaf(w0.w, kA.w, cv);
                cv = fmaf(w1.x, kB.x, cv); cv = fmaf(w1.y, kB.y, cv);
                cv = fmaf(w1.z, kB.z, cv); cv = fmaf(w1.w, kB.w, cv);
                cv = fmaf(w2.x, kC.x, cv); cv = fmaf(w2.y, kC.y, cv);
                cv = fmaf(w2.z, kC.z, cv); cv = fmaf(w2.w, kC.w, cv);
                cv = fmaf(w3.x, kD.x, cv); cv = fmaf(w3.y, kD.y, cv);
                cv = fmaf(w3.z, kD.z, cv); cv = fmaf(w3.w, kD.w, cv);
                int j = d - d0;
                if (d + 1 < dend) {
                    w0 = w2; w1 = w3;
                    w2 = base[2 * j + 4];
                    w3 = base[2 * j + 5];
                }
                a0 = fmaf(cv, __ldg(gate_w + d),             a0);
                a1 = fmaf(cv, __ldg(gate_w + CDIMV + d),     a1);
                a2 = fmaf(cv, __ldg(gate_w + 2 * CDIMV + d), a2);
                a3 = fmaf(cv, __ldg(gate_w + 3 * CDIMV + d), a3);
            }
        }
        float* rp = wbuf + ch * 128 + dl * 4;
        rp[0] = a0; rp[1] = a1; rp[2] = a2; rp[3] = a3;
    }
    __syncthreads();
    if (t < 32) {
        int ch = t >> 2, m = t & 3;
        float s = 0.f;
        #pragma unroll
        for (int dl = 0; dl < 32; dl++) s += wbuf[ch * 128 + dl * 4 + m];
        gts[ch * 4 + m] = s + __ldg(gate_b + m);
    }
    __syncthreads();
    if (t < CPB) {
        float g0 = gts[t * 4], g1 = gts[t * 4 + 1], g2 = gts[t * 4 + 2], g3 = gts[t * 4 + 3];
        float mx = fmaxf(fmaxf(g0, g1), fmaxf(g2, g3));
        g0 = expf(g0 - mx); g1 = expf(g1 - mx); g2 = expf(g2 - mx); g3 = expf(g3 - mx);
        float inv = 1.f / (g0 + g1 + g2 + g3);
        gts[t * 4]     = g0 * inv;
        gts[t * 4 + 1] = g1 * inv;
        gts[t * 4 + 2] = g2 * inv;
        gts[t * 4 + 3] = g3 * inv;
    }
    __syncthreads();

    // ---- phase 4: two groups of 4 channels: W_eff, map matmul, stage ----
    #pragma unroll 1
    for (int g = 0; g < 2; g++) {
        // build gated effective weight per channel: wbuf[c4][o*60+i]
        for (int p = t; p < NOUTV * NINV; p += NTHR) {
            float m0 = __ldg(map_w + p);
            float m1 = __ldg(map_w + 900 + p);
            float m2 = __ldg(map_w + 1800 + p);
            float m3 = __ldg(map_w + 2700 + p);
            #pragma unroll
            for (int c4 = 0; c4 < 4; c4++) {
                const float* gg = gts + (g * 4 + c4) * 4;
                wbuf[c4 * 900 + p] = gg[0] * m0 + gg[1] * m1 + gg[2] * m2 + gg[3] * m3;
            }
        }
        if (t < 60) {
            int c4 = t / 15, o = t % 15;
            const float* gg = gts + (g * 4 + c4) * 4;
            beff[t] = gg[0] * __ldg(map_b + o)      + gg[1] * __ldg(map_b + 15 + o)
                    + gg[2] * __ldg(map_b + 30 + o) + gg[3] * __ldg(map_b + 45 + o);
        }
        __syncthreads();

        // register-tiled matmul: tile = 3 outputs (o) x 4 preds (s)
        float4 acc0, acc1, acc2;
        int ch4 = 0, o0 = 0, sg = 0;
        const bool active = (t < 240);
        if (active) {
            ch4 = t / 60;
            int rem = t % 60;
            o0 = (rem / 12) * 3;
            sg = rem % 12;
            const float* row = xs + (g * 4 + ch4) * XROW + sg * 4;
            const float* W0 = wbuf + ch4 * 900 + o0 * 60;
            acc0 = make_float4(0.f, 0.f, 0.f, 0.f);
            acc1 = acc0; acc2 = acc0;
            #pragma unroll 6
            for (int i = 0; i < NINV; i++) {
                float4 xv = *(const float4*)(row + i * SEGS);
                float w0 = W0[i], w1 = W0[60 + i], w2 = W0[120 + i];
                acc0.x = fmaf(w0, xv.x, acc0.x);
                acc0.y = fmaf(w0, xv.y, acc0.y);
                acc0.z = fmaf(w0, xv.z, acc0.z);
                acc0.w = fmaf(w0, xv.w, acc0.w);
                acc1.x = fmaf(w1, xv.x, acc1.x);
                acc1.y = fmaf(w1, xv.y, acc1.y);
                acc1.z = fmaf(w1, xv.z, acc1.z);
                acc1.w = fmaf(w1, xv.w, acc1.w);
                acc2.x = fmaf(w2, xv.x, acc2.x);
                acc2.y = fmaf(w2, xv.y, acc2.y);
                acc2.z = fmaf(w2, xv.z, acc2.z);
                acc2.w = fmaf(w2, xv.w, acc2.w);
            }
        }
        __syncthreads();   // all xn/W_eff reads done before staging overwrites xs
        if (active) {
            int ch = g * 4 + ch4;
            float sd = stdv[ch], mu = meanv[ch];
            float* orow = xs + ch * XROW;
            float b0 = beff[ch4 * 15 + o0];
            float b1 = beff[ch4 * 15 + o0 + 1];
            float b2 = beff[ch4 * 15 + o0 + 2];
            float4 r;
            r.x = fmaf(acc0.x + b0, sd, mu);
            r.y = fmaf(acc0.y + b0, sd, mu);
            r.z = fmaf(acc0.z + b0, sd, mu);
            r.w = fmaf(acc0.w + b0, sd, mu);
            *(float4*)(orow + (o0 + 0) * SEGS + sg * 4) = r;
            r.x = fmaf(acc1.x + b1, sd, mu);
            r.y = fmaf(acc1.y + b1, sd, mu);
            r.z = fmaf(acc1.z + b1, sd, mu);
            r.w = fmaf(acc1.w + b1, sd, mu);
            *(float4*)(orow + (o0 + 1) * SEGS + sg * 4) = r;
            r.x = fmaf(acc2.x + b2, sd, mu);
            r.y = fmaf(acc2.y + b2, sd, mu);
            r.z = fmaf(acc2.z + b2, sd, mu);
            r.w = fmaf(acc2.w + b2, sd, mu);
            *(float4*)(orow + (o0 + 2) * SEGS + sg * 4) = r;
        }
        __syncthreads();   // group done; wbuf free for next group
    }

    // ---- phase 5: coalesced output write ----
    {
        const size_t obase = (size_t)b * PREDP * CC + c0;
        for (int idx = t; idx < CPB * PREDP; idx += NTHR) {
            int ch = idx & 7, p = idx >> 3;
            int c = c0 + ch;
            if (c < CC)
                out[obase + (size_t)p * CC + ch] = xs[ch * XROW + p];
        }
    }
}

extern "C" void kernel_launch(void* const* d_in, const int* in_sizes, int n_in,
                              void* d_out, int out_size)
{
    const float* x      = (const float*)d_in[0];
    const float* conv_w = (const float*)d_in[1];
    const float* conv_b = (const float*)d_in[2];
    const float* gate_w = (const float*)d_in[3];
    const float* gate_b = (const float*)d_in[4];
    const float* map_w  = (const float*)d_in[5];
    const float* map_b  = (const float*)d_in[6];
    float* out = (float*)d_out;

    const int smem_bytes = SMEM_FLOATS * (int)sizeof(float);   // 107,696 B
    cudaFuncSetAttribute(fused_model_kernel,
                         cudaFuncAttributeMaxDynamicSharedMemorySize, smem_bytes);

    dim3 grid(BB * CBLKS);   // 3456 blocks
    fused_model_kernel<<<grid, NTHR, smem_bytes>>>(x, conv_w, conv_b, gate_w,
                                                   gate_b, map_w, map_b, out);
}